// round 3
// baseline (speedup 1.0000x reference)
#include <cuda_runtime.h>

// GINE-conv network:
//   h = emb[x]; h = leaky_relu(gine(h, E1)); h2 = gine(h, E2); out = h2 @ h2.T
// N=8192, E=262144, dims 128 -> 64 -> 32, out 8192x8192 f32.
// This revision: packed fma.rn.f32x2 (FFMA2) everywhere + smem-tiled lin1/lin2.

#define NN     8192
#define NE     262144
#define EMB    128
#define D1     64
#define D2     32
#define EPSF   1e-9f
#define SLOPEF 0.01f

typedef unsigned long long u64;

__device__ __align__(16) float g_h[NN * EMB];
__device__ __align__(16) float g_agg1[NN * EMB];
__device__ __align__(16) float g_h1[NN * D1];
__device__ __align__(16) float g_agg2[NN * D1];
__device__ __align__(16) float g_h2[NN * D2];
__device__ int g_x[NN];
__device__ int g_src[NE];
__device__ int g_dst[NE];

__device__ __forceinline__ u64 pack2(float lo, float hi) {
    u64 r; asm("mov.b64 %0, {%1,%2};" : "=l"(r) : "f"(lo), "f"(hi)); return r;
}
__device__ __forceinline__ void unpack2(u64 v, float& lo, float& hi) {
    asm("mov.b64 {%0,%1}, %2;" : "=f"(lo), "=f"(hi) : "l"(v));
}
// d = a * b + d  (packed 2x fp32, bit-exact IEEE per lane)
__device__ __forceinline__ void fma_x2(u64& d, u64 a, u64 b) {
    asm("fma.rn.f32x2 %0, %1, %2, %0;" : "+l"(d) : "l"(a), "l"(b));
}

// ---------------------------------------------------------------------------
// K0: normalize index dtypes (int64 vs int32 delivery; detection as before).
// ---------------------------------------------------------------------------
__global__ void k_convert(const unsigned* __restrict__ xbuf,
                          const unsigned* __restrict__ eibuf) {
    unsigned odd_or = 0;
#pragma unroll
    for (int i = 0; i < 32; i++) odd_or |= eibuf[2 * i + 1];
    bool mode64 = (odd_or == 0);

    int t = blockIdx.x * blockDim.x + threadIdx.x;
    if (t < NE) {
        g_src[t] = (int)(mode64 ? eibuf[2 * t]        : eibuf[t]);
        g_dst[t] = (int)(mode64 ? eibuf[2 * (NE + t)] : eibuf[NE + t]);
    }
    if (t < NN) g_x[t] = (int)(mode64 ? xbuf[2 * t] : xbuf[t]);
}

// ---------------------------------------------------------------------------
// K1: h = emb[x];  agg1 = (1+eps)*h
// ---------------------------------------------------------------------------
__global__ void k_embed(const float4* __restrict__ emb4) {
    int t = blockIdx.x * blockDim.x + threadIdx.x;
    int node = t >> 5;
    int c    = t & 31;
    float4 v = emb4[g_x[node] * 32 + c];
    ((float4*)g_h)[t] = v;
    float4 a = make_float4(v.x * (1.f + EPSF), v.y * (1.f + EPSF),
                           v.z * (1.f + EPSF), v.w * (1.f + EPSF));
    ((float4*)g_agg1)[t] = a;
}

// ---------------------------------------------------------------------------
// K2: edge pass 1. Warp per edge; lane owns 4 cols (2 f32x2 accumulators).
// ---------------------------------------------------------------------------
__global__ void __launch_bounds__(256)
k_edge1(const float4* __restrict__ ea4,
        const float4* __restrict__ w4,     // E1w as (16 x 32) float4
        const float4* __restrict__ b4) {   // E1b as 32 float4
    int lane = threadIdx.x & 31;
    int warp = (blockIdx.x * blockDim.x + threadIdx.x) >> 5;
    int nw   = (gridDim.x * blockDim.x) >> 5;

    u64 wp[16][2];
#pragma unroll
    for (int k = 0; k < 16; k++) {
        float4 w = w4[k * 32 + lane];
        wp[k][0] = pack2(w.x, w.y);
        wp[k][1] = pack2(w.z, w.w);
    }
    float4 bv = b4[lane];
    u64 bias0 = pack2(bv.x, bv.y);
    u64 bias1 = pack2(bv.z, bv.w);

    const float4* h4 = (const float4*)g_h;

    for (int e = warp; e < NE; e += nw) {
        int src = g_src[e];
        int dst = g_dst[e];
        float4 ea0 = ea4[e * 4 + 0];
        float4 ea1 = ea4[e * 4 + 1];
        float4 ea2 = ea4[e * 4 + 2];
        float4 ea3 = ea4[e * 4 + 3];

        u64 acc0 = bias0, acc1 = bias1;
        float s[16] = {ea0.x, ea0.y, ea0.z, ea0.w, ea1.x, ea1.y, ea1.z, ea1.w,
                       ea2.x, ea2.y, ea2.z, ea2.w, ea3.x, ea3.y, ea3.z, ea3.w};
#pragma unroll
        for (int k = 0; k < 16; k++) {
            u64 sp = pack2(s[k], s[k]);
            fma_x2(acc0, sp, wp[k][0]);
            fma_x2(acc1, sp, wp[k][1]);
        }

        float4 hv = h4[src * 32 + lane];
        float a0, a1, a2, a3;
        unpack2(acc0, a0, a1);
        unpack2(acc1, a2, a3);
        float m0 = fmaxf(hv.x + a0, 0.f);
        float m1 = fmaxf(hv.y + a1, 0.f);
        float m2 = fmaxf(hv.z + a2, 0.f);
        float m3 = fmaxf(hv.w + a3, 0.f);

        float* p = g_agg1 + (size_t)dst * EMB + lane * 4;
        asm volatile("red.global.add.v4.f32 [%0], {%1,%2,%3,%4};"
                     :: "l"(p), "f"(m0), "f"(m1), "f"(m2), "f"(m3)
                     : "memory");
    }
}

// ---------------------------------------------------------------------------
// K3: h1 = leaky_relu(agg1 @ W1 + b1);  agg2 = (1+eps)*h1
// 64 nodes/block, 256 threads: thread = 2 nodes x 8 cols (4 f32x2 accs each).
// K=128 tiled by 64. W tile + row tile in smem; w-loads broadcast-dedup.
// ---------------------------------------------------------------------------
#define L1_NODES 64
#define L1_KT    64
__global__ void __launch_bounds__(256)
k_lin1(const float* __restrict__ W1, const float* __restrict__ b1) {
    __shared__ float srow[L1_NODES][L1_KT + 4];   // pad 68: distinct banks/node
    __shared__ u64   sW2[L1_KT][D1 / 2];          // 16 KB

    int tid  = threadIdx.x;
    int cg   = tid & 7;          // 8 col-groups of 8 cols
    int n0   = (tid >> 3) * 2;   // node pair within block
    int node0 = blockIdx.x * L1_NODES;

    u64 accA[4], accB[4];
#pragma unroll
    for (int p = 0; p < 4; p++) {
        u64 bp = pack2(b1[cg * 8 + 2 * p], b1[cg * 8 + 2 * p + 1]);
        accA[p] = bp; accB[p] = bp;
    }

    for (int kt = 0; kt < EMB; kt += L1_KT) {
        // stage W tile: W1[(kt+kk)*64 + c] as pairs
        for (int i = tid; i < L1_KT * (D1 / 2); i += 256) {
            int kk = i >> 5, c2 = i & 31;
            float2 v = ((const float2*)W1)[(kt + kk) * (D1 / 2) + c2];
            sW2[kk][c2] = pack2(v.x, v.y);
        }
        // stage row tile (float4, coalesced)
        for (int i = tid; i < L1_NODES * (L1_KT / 4); i += 256) {
            int n = i >> 4, kq = i & 15;
            float4 v = *(const float4*)(g_agg1 + (size_t)(node0 + n) * EMB + kt + kq * 4);
            srow[n][kq * 4 + 0] = v.x; srow[n][kq * 4 + 1] = v.y;
            srow[n][kq * 4 + 2] = v.z; srow[n][kq * 4 + 3] = v.w;
        }
        __syncthreads();

#pragma unroll 4
        for (int kk = 0; kk < L1_KT; kk++) {
            float r0 = srow[n0][kk];
            float r1 = srow[n0 + 1][kk];
            u64 r0p = pack2(r0, r0);
            u64 r1p = pack2(r1, r1);
#pragma unroll
            for (int p = 0; p < 4; p++) {
                u64 w = sW2[kk][cg * 4 + p];
                fma_x2(accA[p], r0p, w);
                fma_x2(accB[p], r1p, w);
            }
        }
        __syncthreads();
    }

    int na = node0 + n0;
#pragma unroll
    for (int p = 0; p < 4; p++) {
        float v0, v1;
        unpack2(accA[p], v0, v1);
        float a0 = v0 >= 0.f ? v0 : SLOPEF * v0;
        float a1 = v1 >= 0.f ? v1 : SLOPEF * v1;
        g_h1[na * D1 + cg * 8 + 2 * p]     = a0;
        g_h1[na * D1 + cg * 8 + 2 * p + 1] = a1;
        g_agg2[na * D1 + cg * 8 + 2 * p]     = (1.f + EPSF) * a0;
        g_agg2[na * D1 + cg * 8 + 2 * p + 1] = (1.f + EPSF) * a1;
        unpack2(accB[p], v0, v1);
        a0 = v0 >= 0.f ? v0 : SLOPEF * v0;
        a1 = v1 >= 0.f ? v1 : SLOPEF * v1;
        g_h1[(na + 1) * D1 + cg * 8 + 2 * p]     = a0;
        g_h1[(na + 1) * D1 + cg * 8 + 2 * p + 1] = a1;
        g_agg2[(na + 1) * D1 + cg * 8 + 2 * p]     = (1.f + EPSF) * a0;
        g_agg2[(na + 1) * D1 + cg * 8 + 2 * p + 1] = (1.f + EPSF) * a1;
    }
}

// ---------------------------------------------------------------------------
// K4: edge pass 2. Warp per edge; lane owns 2 cols (1 f32x2 accumulator).
// ---------------------------------------------------------------------------
__global__ void __launch_bounds__(256)
k_edge2(const float4* __restrict__ ea4,
        const float2* __restrict__ w2v,    // E2w as (16 x 32) float2
        const float2* __restrict__ b2v) {  // E2b as 32 float2
    int lane = threadIdx.x & 31;
    int warp = (blockIdx.x * blockDim.x + threadIdx.x) >> 5;
    int nw   = (gridDim.x * blockDim.x) >> 5;

    u64 wp[16];
#pragma unroll
    for (int k = 0; k < 16; k++) {
        float2 w = w2v[k * 32 + lane];
        wp[k] = pack2(w.x, w.y);
    }
    float2 bv = b2v[lane];
    u64 bias = pack2(bv.x, bv.y);

    const float2* h2v = (const float2*)g_h1;

    for (int e = warp; e < NE; e += nw) {
        int src = g_src[e];
        int dst = g_dst[e];
        float4 ea0 = ea4[e * 4 + 0];
        float4 ea1 = ea4[e * 4 + 1];
        float4 ea2 = ea4[e * 4 + 2];
        float4 ea3 = ea4[e * 4 + 3];

        u64 acc = bias;
        float s[16] = {ea0.x, ea0.y, ea0.z, ea0.w, ea1.x, ea1.y, ea1.z, ea1.w,
                       ea2.x, ea2.y, ea2.z, ea2.w, ea3.x, ea3.y, ea3.z, ea3.w};
#pragma unroll
        for (int k = 0; k < 16; k++) {
            u64 sp = pack2(s[k], s[k]);
            fma_x2(acc, sp, wp[k]);
        }

        float2 hv = h2v[src * 32 + lane];
        float a0, a1;
        unpack2(acc, a0, a1);
        float m0 = fmaxf(hv.x + a0, 0.f);
        float m1 = fmaxf(hv.y + a1, 0.f);

        float* p = g_agg2 + (size_t)dst * D1 + lane * 2;
        asm volatile("red.global.add.v2.f32 [%0], {%1,%2};"
                     :: "l"(p), "f"(m0), "f"(m1)
                     : "memory");
    }
}

// ---------------------------------------------------------------------------
// K5: h2 = agg2 @ W2 + b2.  128 nodes/block, thread = 2 nodes x 8 cols.
// ---------------------------------------------------------------------------
#define L2_NODES 128
__global__ void __launch_bounds__(256)
k_lin2(const float* __restrict__ W2, const float* __restrict__ b2) {
    __shared__ float srow[L2_NODES][D1 + 4];   // 34.8 KB (pad 68)
    __shared__ u64   sW2[D1][D2 / 2];          // 8 KB

    int tid  = threadIdx.x;
    int cg   = tid & 3;          // 4 col-groups of 8 cols
    int n0   = (tid >> 2) * 2;   // node pair
    int node0 = blockIdx.x * L2_NODES;

    for (int i = tid; i < D1 * (D2 / 2); i += 256) {
        int kk = i >> 4, c2 = i & 15;
        float2 v = ((const float2*)W2)[kk * (D2 / 2) + c2];
        sW2[kk][c2] = pack2(v.x, v.y);
    }
    for (int i = tid; i < L2_NODES * (D1 / 4); i += 256) {
        int n = i >> 4, kq = i & 15;
        float4 v = *(const float4*)(g_agg2 + (size_t)(node0 + n) * D1 + kq * 4);
        srow[n][kq * 4 + 0] = v.x; srow[n][kq * 4 + 1] = v.y;
        srow[n][kq * 4 + 2] = v.z; srow[n][kq * 4 + 3] = v.w;
    }
    __syncthreads();

    u64 accA[4], accB[4];
#pragma unroll
    for (int p = 0; p < 4; p++) {
        u64 bp = pack2(b2[cg * 8 + 2 * p], b2[cg * 8 + 2 * p + 1]);
        accA[p] = bp; accB[p] = bp;
    }

#pragma unroll 4
    for (int kk = 0; kk < D1; kk++) {
        float r0 = srow[n0][kk];
        float r1 = srow[n0 + 1][kk];
        u64 r0p = pack2(r0, r0);
        u64 r1p = pack2(r1, r1);
#pragma unroll
        for (int p = 0; p < 4; p++) {
            u64 w = sW2[kk][cg * 4 + p];
            fma_x2(accA[p], r0p, w);
            fma_x2(accB[p], r1p, w);
        }
    }

    int na = node0 + n0;
#pragma unroll
    for (int p = 0; p < 4; p++) {
        float v0, v1;
        unpack2(accA[p], v0, v1);
        g_h2[na * D2 + cg * 8 + 2 * p]     = v0;
        g_h2[na * D2 + cg * 8 + 2 * p + 1] = v1;
        unpack2(accB[p], v0, v1);
        g_h2[(na + 1) * D2 + cg * 8 + 2 * p]     = v0;
        g_h2[(na + 1) * D2 + cg * 8 + 2 * p + 1] = v1;
    }
}

// ---------------------------------------------------------------------------
// K6: C = h2 @ h2^T, symmetric (upper-tri tiles + mirrored writes).
// 128x128 tile, 256 threads, 8x8 per thread via f32x2 (acc as 8x4 pairs).
// Smem tiles stored k-major with even u64-friendly stride.
// ---------------------------------------------------------------------------
#define GP2 65   // row stride in u64 (=130 floats, even, 8B aligned)

__global__ void __launch_bounds__(256)
k_gemm(float* __restrict__ C) {
    int bi = blockIdx.y;
    int bj = blockIdx.x;
    if (bj < bi) return;

    __shared__ u64 As2[D2][GP2];
    __shared__ u64 Bs2[D2][GP2];

    int tid = threadIdx.x;
    for (int i = tid; i < 128 * D2; i += 256) {
        int r = i >> 5;
        int k = i & 31;
        ((float*)As2[k])[r] = g_h2[(bi * 128 + r) * D2 + k];
        ((float*)Bs2[k])[r] = g_h2[(bj * 128 + r) * D2 + k];
    }
    __syncthreads();

    int tx = tid & 15;
    int ty = tid >> 4;
    int i0 = ty * 8;
    int j0 = tx * 8;   // even

    u64 acc2[8][4];
#pragma unroll
    for (int ii = 0; ii < 8; ii++)
#pragma unroll
        for (int jp = 0; jp < 4; jp++) acc2[ii][jp] = 0ull;

#pragma unroll 4
    for (int k = 0; k < D2; k++) {
        u64 b2r[4];
#pragma unroll
        for (int jp = 0; jp < 4; jp++) b2r[jp] = Bs2[k][(j0 >> 1) + jp];
        u64 a2[8];
#pragma unroll
        for (int ii = 0; ii < 8; ii++) {
            float av = ((const float*)As2[k])[i0 + ii];
            a2[ii] = pack2(av, av);
        }
#pragma unroll
        for (int ii = 0; ii < 8; ii++)
#pragma unroll
            for (int jp = 0; jp < 4; jp++)
                fma_x2(acc2[ii][jp], a2[ii], b2r[jp]);
    }

    float acc[8][8];
#pragma unroll
    for (int ii = 0; ii < 8; ii++)
#pragma unroll
        for (int jp = 0; jp < 4; jp++)
            unpack2(acc2[ii][jp], acc[ii][2 * jp], acc[ii][2 * jp + 1]);

    {
        float* Cp = C + (size_t)(bi * 128 + i0) * NN + bj * 128 + j0;
#pragma unroll
        for (int ii = 0; ii < 8; ii++) {
            float4 v0 = make_float4(acc[ii][0], acc[ii][1], acc[ii][2], acc[ii][3]);
            float4 v1 = make_float4(acc[ii][4], acc[ii][5], acc[ii][6], acc[ii][7]);
            ((float4*)(Cp + (size_t)ii * NN))[0] = v0;
            ((float4*)(Cp + (size_t)ii * NN))[1] = v1;
        }
    }
    if (bi != bj) {
        float* Cp = C + (size_t)(bj * 128 + j0) * NN + bi * 128 + i0;
#pragma unroll
        for (int jj = 0; jj < 8; jj++) {
            float4 v0 = make_float4(acc[0][jj], acc[1][jj], acc[2][jj], acc[3][jj]);
            float4 v1 = make_float4(acc[4][jj], acc[5][jj], acc[6][jj], acc[7][jj]);
            ((float4*)(Cp + (size_t)jj * NN))[0] = v0;
            ((float4*)(Cp + (size_t)jj * NN))[1] = v1;
        }
    }
}

// ---------------------------------------------------------------------------
extern "C" void kernel_launch(void* const* d_in, const int* in_sizes, int n_in,
                              void* d_out, int out_size) {
    const unsigned* xbuf  = (const unsigned*)d_in[0];
    const unsigned* eibuf = (const unsigned*)d_in[1];
    const float*    ea    = (const float*)d_in[2];
    const float*    emb   = (const float*)d_in[3];
    const float*    W1    = (const float*)d_in[4];
    const float*    b1    = (const float*)d_in[5];
    const float*    E1w   = (const float*)d_in[6];
    const float*    E1b   = (const float*)d_in[7];
    const float*    W2    = (const float*)d_in[8];
    const float*    b2    = (const float*)d_in[9];
    const float*    E2w   = (const float*)d_in[10];
    const float*    E2b   = (const float*)d_in[11];
    float* out = (float*)d_out;

    k_convert<<<(NE + 255) / 256, 256>>>(xbuf, eibuf);
    k_embed<<<NN * 32 / 256, 256>>>((const float4*)emb);
    k_edge1<<<2048, 256>>>((const float4*)ea,
                           (const float4*)E1w, (const float4*)E1b);
    k_lin1<<<NN / L1_NODES, 256>>>(W1, b1);
    k_edge2<<<2048, 256>>>((const float4*)ea,
                           (const float2*)E2w, (const float2*)E2b);
    k_lin2<<<NN / L2_NODES, 256>>>(W2, b2);
    dim3 g(NN / 128, NN / 128);
    k_gemm<<<g, 256>>>(out);
}

// round 4
// speedup vs baseline: 1.2604x; 1.2604x over previous
#include <cuda_runtime.h>

// GINE-conv network:
//   h = emb[x]; h = leaky_relu(gine(h, E1)); h2 = gine(h, E2); out = h2 @ h2.T
// N=8192, E=262144, dims 128 -> 64 -> 32, out 8192x8192 f32.
// R4: R2-validated edge kernels; warp-per-node lin1/lin2; f32x2 only in gemm.

#define NN     8192
#define NE     262144
#define EMB    128
#define D1     64
#define D2     32
#define EPSF   1e-9f
#define SLOPEF 0.01f

typedef unsigned long long u64;

__device__ __align__(16) float g_h[NN * EMB];
__device__ __align__(16) float g_agg1[NN * EMB];
__device__ __align__(16) float g_h1[NN * D1];
__device__ __align__(16) float g_agg2[NN * D1];
__device__ __align__(16) float g_h2[NN * D2];
__device__ int g_x[NN];
__device__ int g_src[NE];
__device__ int g_dst[NE];

__device__ __forceinline__ u64 pack2(float lo, float hi) {
    u64 r; asm("mov.b64 %0, {%1,%2};" : "=l"(r) : "f"(lo), "f"(hi)); return r;
}
__device__ __forceinline__ void unpack2(u64 v, float& lo, float& hi) {
    asm("mov.b64 {%0,%1}, %2;" : "=f"(lo), "=f"(hi) : "l"(v));
}
// d = a * b + d  (packed 2x fp32, bit-exact IEEE per lane)
__device__ __forceinline__ void fma_x2(u64& d, u64 a, u64 b) {
    asm("fma.rn.f32x2 %0, %1, %2, %0;" : "+l"(d) : "l"(a), "l"(b));
}

__device__ __forceinline__ void fma4(float4& a, float s, const float4& w) {
    a.x = fmaf(s, w.x, a.x);
    a.y = fmaf(s, w.y, a.y);
    a.z = fmaf(s, w.z, a.z);
    a.w = fmaf(s, w.w, a.w);
}
__device__ __forceinline__ void fma2s(float2& a, float s, const float2& w) {
    a.x = fmaf(s, w.x, a.x);
    a.y = fmaf(s, w.y, a.y);
}

// ---------------------------------------------------------------------------
// K0: normalize index dtypes (int64 vs int32 delivery; detection as before).
// ---------------------------------------------------------------------------
__global__ void k_convert(const unsigned* __restrict__ xbuf,
                          const unsigned* __restrict__ eibuf) {
    unsigned odd_or = 0;
#pragma unroll
    for (int i = 0; i < 32; i++) odd_or |= eibuf[2 * i + 1];
    bool mode64 = (odd_or == 0);

    int t = blockIdx.x * blockDim.x + threadIdx.x;
    if (t < NE) {
        g_src[t] = (int)(mode64 ? eibuf[2 * t]        : eibuf[t]);
        g_dst[t] = (int)(mode64 ? eibuf[2 * (NE + t)] : eibuf[NE + t]);
    }
    if (t < NN) g_x[t] = (int)(mode64 ? xbuf[2 * t] : xbuf[t]);
}

// ---------------------------------------------------------------------------
// K1: h = emb[x];  agg1 = (1+eps)*h
// ---------------------------------------------------------------------------
__global__ void k_embed(const float4* __restrict__ emb4) {
    int t = blockIdx.x * blockDim.x + threadIdx.x;
    int node = t >> 5;
    int c    = t & 31;
    float4 v = emb4[g_x[node] * 32 + c];
    ((float4*)g_h)[t] = v;
    float4 a = make_float4(v.x * (1.f + EPSF), v.y * (1.f + EPSF),
                           v.z * (1.f + EPSF), v.w * (1.f + EPSF));
    ((float4*)g_agg1)[t] = a;
}

// ---------------------------------------------------------------------------
// K2: edge pass 1 (R2-validated). Warp per edge; lane owns 4 cols.
// ---------------------------------------------------------------------------
__global__ void __launch_bounds__(256)
k_edge1(const float4* __restrict__ ea4,
        const float4* __restrict__ w4,     // E1w as (16 x 32) float4
        const float4* __restrict__ b4) {   // E1b as 32 float4
    int lane = threadIdx.x & 31;
    int warp = (blockIdx.x * blockDim.x + threadIdx.x) >> 5;
    int nw   = (gridDim.x * blockDim.x) >> 5;

    float4 w[16];
#pragma unroll
    for (int k = 0; k < 16; k++) w[k] = w4[k * 32 + lane];
    float4 bias = b4[lane];

    const float4* h4 = (const float4*)g_h;

    for (int e = warp; e < NE; e += nw) {
        int src = g_src[e];
        int dst = g_dst[e];
        float4 ea0 = ea4[e * 4 + 0];
        float4 ea1 = ea4[e * 4 + 1];
        float4 ea2 = ea4[e * 4 + 2];
        float4 ea3 = ea4[e * 4 + 3];

        float4 acc = bias;
        fma4(acc, ea0.x, w[0]);  fma4(acc, ea0.y, w[1]);
        fma4(acc, ea0.z, w[2]);  fma4(acc, ea0.w, w[3]);
        fma4(acc, ea1.x, w[4]);  fma4(acc, ea1.y, w[5]);
        fma4(acc, ea1.z, w[6]);  fma4(acc, ea1.w, w[7]);
        fma4(acc, ea2.x, w[8]);  fma4(acc, ea2.y, w[9]);
        fma4(acc, ea2.z, w[10]); fma4(acc, ea2.w, w[11]);
        fma4(acc, ea3.x, w[12]); fma4(acc, ea3.y, w[13]);
        fma4(acc, ea3.z, w[14]); fma4(acc, ea3.w, w[15]);

        float4 hv = h4[src * 32 + lane];
        float m0 = fmaxf(hv.x + acc.x, 0.f);
        float m1 = fmaxf(hv.y + acc.y, 0.f);
        float m2 = fmaxf(hv.z + acc.z, 0.f);
        float m3 = fmaxf(hv.w + acc.w, 0.f);

        float* p = g_agg1 + (size_t)dst * EMB + lane * 4;
        asm volatile("red.global.add.v4.f32 [%0], {%1,%2,%3,%4};"
                     :: "l"(p), "f"(m0), "f"(m1), "f"(m2), "f"(m3)
                     : "memory");
    }
}

// ---------------------------------------------------------------------------
// K3: h1 = leaky_relu(agg1 @ W1 + b1);  agg2 = (1+eps)*h1
// Warp per node; lane owns 2 cols. W1 in smem as float2. grid = NN/8 = 1024.
// Per k: 1 broadcast LDS (row) + 1 LDS.64 (w) + 2 FFMA.
// ---------------------------------------------------------------------------
__global__ void __launch_bounds__(256)
k_lin1(const float* __restrict__ W1, const float* __restrict__ b1) {
    __shared__ float2 sW[EMB][D1 / 2];     // 32 KB, [k][c2]
    __shared__ float  srow[8][EMB + 4];    // 4.2 KB

    int tid  = threadIdx.x;
    int warp = tid >> 5;
    int lane = tid & 31;

    for (int i = tid; i < EMB * (D1 / 2); i += 256)
        sW[i >> 5][i & 31] = ((const float2*)W1)[i];

    int n = blockIdx.x * 8 + warp;
    float4 v = *(const float4*)(g_agg1 + (size_t)n * EMB + lane * 4);
    *(float4*)&srow[warp][lane * 4] = v;
    __syncthreads();

    float2 acc = ((const float2*)b1)[lane];
#pragma unroll
    for (int k = 0; k < EMB; k++) {
        float r = srow[warp][k];
        float2 w = sW[k][lane];
        acc.x = fmaf(r, w.x, acc.x);
        acc.y = fmaf(r, w.y, acc.y);
    }

    float a0 = acc.x >= 0.f ? acc.x : SLOPEF * acc.x;
    float a1 = acc.y >= 0.f ? acc.y : SLOPEF * acc.y;
    ((float2*)(g_h1   + (size_t)n * D1))[lane] = make_float2(a0, a1);
    ((float2*)(g_agg2 + (size_t)n * D1))[lane] =
        make_float2((1.f + EPSF) * a0, (1.f + EPSF) * a1);
}

// ---------------------------------------------------------------------------
// K4: edge pass 2 (R2-validated). Warp per edge; lane owns 2 cols.
// ---------------------------------------------------------------------------
__global__ void __launch_bounds__(256)
k_edge2(const float4* __restrict__ ea4,
        const float2* __restrict__ w2v,    // E2w as (16 x 32) float2
        const float2* __restrict__ b2v) {  // E2b as 32 float2
    int lane = threadIdx.x & 31;
    int warp = (blockIdx.x * blockDim.x + threadIdx.x) >> 5;
    int nw   = (gridDim.x * blockDim.x) >> 5;

    float2 w[16];
#pragma unroll
    for (int k = 0; k < 16; k++) w[k] = w2v[k * 32 + lane];
    float2 bias = b2v[lane];

    const float2* h2v = (const float2*)g_h1;

    for (int e = warp; e < NE; e += nw) {
        int src = g_src[e];
        int dst = g_dst[e];
        float4 ea0 = ea4[e * 4 + 0];
        float4 ea1 = ea4[e * 4 + 1];
        float4 ea2 = ea4[e * 4 + 2];
        float4 ea3 = ea4[e * 4 + 3];

        float2 acc = bias;
        fma2s(acc, ea0.x, w[0]);  fma2s(acc, ea0.y, w[1]);
        fma2s(acc, ea0.z, w[2]);  fma2s(acc, ea0.w, w[3]);
        fma2s(acc, ea1.x, w[4]);  fma2s(acc, ea1.y, w[5]);
        fma2s(acc, ea1.z, w[6]);  fma2s(acc, ea1.w, w[7]);
        fma2s(acc, ea2.x, w[8]);  fma2s(acc, ea2.y, w[9]);
        fma2s(acc, ea2.z, w[10]); fma2s(acc, ea2.w, w[11]);
        fma2s(acc, ea3.x, w[12]); fma2s(acc, ea3.y, w[13]);
        fma2s(acc, ea3.z, w[14]); fma2s(acc, ea3.w, w[15]);

        float2 hv = h2v[src * 32 + lane];
        float m0 = fmaxf(hv.x + acc.x, 0.f);
        float m1 = fmaxf(hv.y + acc.y, 0.f);

        float* p = g_agg2 + (size_t)dst * D1 + lane * 2;
        asm volatile("red.global.add.v2.f32 [%0], {%1,%2};"
                     :: "l"(p), "f"(m0), "f"(m1)
                     : "memory");
    }
}

// ---------------------------------------------------------------------------
// K5: h2 = agg2 @ W2 + b2.  Warp per node; lane owns 1 col. grid = 1024.
// ---------------------------------------------------------------------------
__global__ void __launch_bounds__(256)
k_lin2(const float* __restrict__ W2, const float* __restrict__ b2) {
    __shared__ float sW[D1][D2 + 1];      // pad 33: conflict-free columns
    __shared__ float srow[8][D1 + 4];

    int tid  = threadIdx.x;
    int warp = tid >> 5;
    int lane = tid & 31;

    for (int i = tid; i < D1 * D2; i += 256)
        sW[i >> 5][i & 31] = W2[i];

    int n = blockIdx.x * 8 + warp;
    float2 rv = *(const float2*)(g_agg2 + (size_t)n * D1 + lane * 2);
    srow[warp][lane * 2]     = rv.x;
    srow[warp][lane * 2 + 1] = rv.y;
    __syncthreads();

    float acc = b2[lane];
#pragma unroll
    for (int k = 0; k < D1; k++)
        acc = fmaf(srow[warp][k], sW[k][lane], acc);

    g_h2[(size_t)n * D2 + lane] = acc;
}

// ---------------------------------------------------------------------------
// K6: C = h2 @ h2^T, symmetric (upper-tri tiles + mirrored writes).
// 128x128 tile, 256 threads, 8x8 per thread. Inner product via fma.rn.f32x2:
// b read directly as u64 pairs from smem, a splat-packed per k.
// ---------------------------------------------------------------------------
__global__ void __launch_bounds__(256)
k_gemm(float* __restrict__ C) {
    int bi = blockIdx.y;
    int bj = blockIdx.x;
    if (bj < bi) return;

    __shared__ float As[D2][128];   // 16 KB, [k][row], 16B-aligned rows
    __shared__ float Bs[D2][128];   // 16 KB

    int tid = threadIdx.x;
    for (int i = tid; i < 128 * D2; i += 256) {
        int r = i >> 5;
        int k = i & 31;
        As[k][r] = g_h2[(size_t)(bi * 128 + r) * D2 + k];
        Bs[k][r] = g_h2[(size_t)(bj * 128 + r) * D2 + k];
    }
    __syncthreads();

    int tx = tid & 15;
    int ty = tid >> 4;
    int i0 = ty * 8;
    int j0 = tx * 8;   // even

    u64 acc2[8][4];
#pragma unroll
    for (int ii = 0; ii < 8; ii++)
#pragma unroll
        for (int jp = 0; jp < 4; jp++) acc2[ii][jp] = 0ull;

#pragma unroll 4
    for (int k = 0; k < D2; k++) {
        u64 b2r[4];
        const u64* brow = (const u64*)&Bs[k][0];
#pragma unroll
        for (int jp = 0; jp < 4; jp++) b2r[jp] = brow[(j0 >> 1) + jp];

        float4 av0 = *(const float4*)&As[k][i0];
        float4 av1 = *(const float4*)&As[k][i0 + 4];
        u64 a2[8];
        a2[0] = pack2(av0.x, av0.x); a2[1] = pack2(av0.y, av0.y);
        a2[2] = pack2(av0.z, av0.z); a2[3] = pack2(av0.w, av0.w);
        a2[4] = pack2(av1.x, av1.x); a2[5] = pack2(av1.y, av1.y);
        a2[6] = pack2(av1.z, av1.z); a2[7] = pack2(av1.w, av1.w);

#pragma unroll
        for (int ii = 0; ii < 8; ii++)
#pragma unroll
            for (int jp = 0; jp < 4; jp++)
                fma_x2(acc2[ii][jp], a2[ii], b2r[jp]);
    }

    float acc[8][8];
#pragma unroll
    for (int ii = 0; ii < 8; ii++)
#pragma unroll
        for (int jp = 0; jp < 4; jp++)
            unpack2(acc2[ii][jp], acc[ii][2 * jp], acc[ii][2 * jp + 1]);

    {
        float* Cp = C + (size_t)(bi * 128 + i0) * NN + bj * 128 + j0;
#pragma unroll
        for (int ii = 0; ii < 8; ii++) {
            float4 v0 = make_float4(acc[ii][0], acc[ii][1], acc[ii][2], acc[ii][3]);
            float4 v1 = make_float4(acc[ii][4], acc[ii][5], acc[ii][6], acc[ii][7]);
            ((float4*)(Cp + (size_t)ii * NN))[0] = v0;
            ((float4*)(Cp + (size_t)ii * NN))[1] = v1;
        }
    }
    if (bi != bj) {
        float* Cp = C + (size_t)(bj * 128 + j0) * NN + bi * 128 + i0;
#pragma unroll
        for (int jj = 0; jj < 8; jj++) {
            float4 v0 = make_float4(acc[0][jj], acc[1][jj], acc[2][jj], acc[3][jj]);
            float4 v1 = make_float4(acc[4][jj], acc[5][jj], acc[6][jj], acc[7][jj]);
            ((float4*)(Cp + (size_t)jj * NN))[0] = v0;
            ((float4*)(Cp + (size_t)jj * NN))[1] = v1;
        }
    }
}

// ---------------------------------------------------------------------------
extern "C" void kernel_launch(void* const* d_in, const int* in_sizes, int n_in,
                              void* d_out, int out_size) {
    const unsigned* xbuf  = (const unsigned*)d_in[0];
    const unsigned* eibuf = (const unsigned*)d_in[1];
    const float*    ea    = (const float*)d_in[2];
    const float*    emb   = (const float*)d_in[3];
    const float*    W1    = (const float*)d_in[4];
    const float*    b1    = (const float*)d_in[5];
    const float*    E1w   = (const float*)d_in[6];
    const float*    E1b   = (const float*)d_in[7];
    const float*    W2    = (const float*)d_in[8];
    const float*    b2    = (const float*)d_in[9];
    const float*    E2w   = (const float*)d_in[10];
    const float*    E2b   = (const float*)d_in[11];
    float* out = (float*)d_out;

    k_convert<<<(NE + 255) / 256, 256>>>(xbuf, eibuf);
    k_embed<<<NN * 32 / 256, 256>>>((const float4*)emb);
    k_edge1<<<2048, 256>>>((const float4*)ea,
                           (const float4*)E1w, (const float4*)E1b);
    k_lin1<<<NN / 8, 256>>>(W1, b1);
    k_edge2<<<2048, 256>>>((const float4*)ea,
                           (const float2*)E2w, (const float2*)E2b);
    k_lin2<<<NN / 8, 256>>>(W2, b2);
    dim3 g(NN / 128, NN / 128);
    k_gemm<<<g, 256>>>(out);
}